// round 3
// baseline (speedup 1.0000x reference)
#include <cuda_runtime.h>
#include <cstdint>

// ---------------------------------------------------------------------------
// Threefry-2x32, FULL 20 rounds (5 groups of 4) + 6 key injections,
// bit-exact match of JAX's threefry PRNG (jax/_src/prng.py).
// ---------------------------------------------------------------------------
#define TF_ROUND(r) do { x0 += x1; x1 = (x1 << (r)) | (x1 >> (32 - (r))); x1 ^= x0; } while (0)

__host__ __device__ __forceinline__ void tf2x32(uint32_t k0, uint32_t k1,
                                                uint32_t x0, uint32_t x1,
                                                uint32_t& o0, uint32_t& o1) {
    uint32_t k2 = k0 ^ k1 ^ 0x1BD11BDAu;
    x0 += k0; x1 += k1;                                   // inject s=0
    TF_ROUND(13); TF_ROUND(15); TF_ROUND(26); TF_ROUND(6);
    x0 += k1; x1 += k2 + 1u;                              // s=1
    TF_ROUND(17); TF_ROUND(29); TF_ROUND(16); TF_ROUND(24);
    x0 += k2; x1 += k0 + 2u;                              // s=2
    TF_ROUND(13); TF_ROUND(15); TF_ROUND(26); TF_ROUND(6);
    x0 += k0; x1 += k1 + 3u;                              // s=3
    TF_ROUND(17); TF_ROUND(29); TF_ROUND(16); TF_ROUND(24);
    x0 += k1; x1 += k2 + 4u;                              // s=4
    TF_ROUND(13); TF_ROUND(15); TF_ROUND(26); TF_ROUND(6);   // rounds 17-20
    x0 += k2; x1 += k0 + 5u;                              // s=5 (final)
    o0 = x0; o1 = x1;
}

// Partitionable threefry random_bits: element j -> counter64 j -> block (0, j),
// 32-bit draw = o0 ^ o1.
__device__ __forceinline__ uint32_t tfbits(uint32_t k0, uint32_t k1, uint32_t j) {
    uint32_t o0, o1;
    tf2x32(k0, k1, 0u, j, o0, o1);
    return o0 ^ o1;
}

// JAX uniform(minval=tiny, maxval=1).
__device__ __forceinline__ float jax_uniform(uint32_t bits) {
    const float TINY = 1.17549435e-38f;
    float f = __uint_as_float((bits >> 9) | 0x3f800000u) - 1.0f;
    return fmaxf(TINY, f + TINY);
}

// argmax(c + gumbel) over 2 entries; index-0 wins ties.
// Equal counts -> gumbel monotone in (bits>>9): EXACT integer compare.
__device__ __forceinline__ bool decide(float c0, float c1, uint32_t b0, uint32_t b1) {
    if (c0 == c1) return (b1 >> 9) > (b0 >> 9);
    float g0 = -logf(-logf(jax_uniform(b0)));
    float g1 = -logf(-logf(jax_uniform(b1)));
    return (c1 + g1) > (c0 + g0);
}

// ---------------------------------------------------------------------------
// Static scratch (no allocations allowed)
// ---------------------------------------------------------------------------
#define B_SZ  128
#define F0    1024   // in_features
#define F1    512    // hidden

__device__ int                 g_op0[F1];
__device__ int                 g_op1[F0];
__device__ uint32_t            g_mask0[F1 * (F0 / 32)];
__device__ uint32_t            g_mask1[F0 * (F1 / 32)];
__device__ unsigned long long  g_skey0[B_SZ * F0];
__device__ unsigned long long  g_skey1[B_SZ * F1];
__device__ float               g_h[B_SZ * F1];

// ---------------------------------------------------------------------------
// Kernel 1: operator selection per output neuron.
// ---------------------------------------------------------------------------
__global__ void op_kernel(uint32_t k0, uint32_t k1, const float* __restrict__ otc,
                          int* __restrict__ opidx, int out) {
    int o = blockIdx.x * blockDim.x + threadIdx.x;
    if (o >= out) return;
    uint32_t b0 = tfbits(k0, k1, (uint32_t)(2 * o));
    uint32_t b1 = tfbits(k0, k1, (uint32_t)(2 * o + 1));
    float c0 = otc[2 * o], c1 = otc[2 * o + 1];
    opidx[o] = decide(c0, c1, b0, b1) ? 1 : 0;
}

// ---------------------------------------------------------------------------
// Kernel 2: edge-mask generation. Thread = (o, i), only the CHOSEN op plane.
// etc flat(o,op,i,et) = ((o*2+op)*in + i)*2 + et.
// ---------------------------------------------------------------------------
__global__ void mask_kernel(uint32_t k0, uint32_t k1,
                            const float* __restrict__ etc,
                            const int* __restrict__ opidx,
                            uint32_t* __restrict__ maskbits,
                            int in, int log2in) {
    int t = blockIdx.x * blockDim.x + threadIdx.x;
    int i = t & (in - 1);
    int o = t >> log2in;

    int op = opidx[o];                                // warp-uniform
    uint32_t m = (((uint32_t)(o * 2 + op)) << log2in) + (uint32_t)i;
    uint32_t b0 = tfbits(k0, k1, 2u * m);             // et = 0 (no_edge)
    uint32_t b1 = tfbits(k0, k1, 2u * m + 1u);        // et = 1 (normal_edge)

    size_t base = (size_t)m * 2;
    bool sel = decide(etc[base], etc[base + 1], b0, b1);

    unsigned msk = __ballot_sync(0xffffffffu, sel);
    if ((threadIdx.x & 31) == 0) {
        int nw = in >> 5;
        maskbits[o * nw + (i >> 5)] = msk;
    }
}

// ---------------------------------------------------------------------------
// Kernel 3: per-batch-row bitonic sort; keys = (clamped float bits << 32)|idx.
// ---------------------------------------------------------------------------
__global__ void sort_kernel(const float* __restrict__ xin,
                            unsigned long long* __restrict__ skey, int n) {
    __shared__ unsigned long long a[1024];
    int b = blockIdx.x;
    int tid = threadIdx.x;
    for (int idx = tid; idx < n; idx += blockDim.x) {
        float v = fmaxf(xin[(size_t)b * n + idx], 0.0f);
        a[idx] = ((unsigned long long)__float_as_uint(v) << 32) | (unsigned)idx;
    }
    __syncthreads();
    for (int k = 2; k <= n; k <<= 1) {
        for (int j = k >> 1; j > 0; j >>= 1) {
            for (int s = tid; s < n; s += blockDim.x) {
                int l = s ^ j;
                if (l > s) {
                    bool up = ((s & k) == 0);
                    unsigned long long va = a[s], vb = a[l];
                    if ((va > vb) == up) { a[s] = vb; a[l] = va; }
                }
            }
            __syncthreads();
        }
    }
    for (int idx = tid; idx < n; idx += blockDim.x)
        skey[(size_t)b * n + idx] = a[idx];
}

// ---------------------------------------------------------------------------
// Kernel 4: probe. Block = neuron o; thread = batch row b.
// ---------------------------------------------------------------------------
__global__ void probe_kernel(const unsigned long long* __restrict__ skey,
                             const uint32_t* __restrict__ maskbits,
                             const int* __restrict__ opidx,
                             float* __restrict__ outp, int out, int in) {
    int o = blockIdx.x;
    int b = threadIdx.x;
    __shared__ uint32_t mrow[32];
    __shared__ int sop;
    int nw = in >> 5;
    if (b < nw) mrow[b] = maskbits[o * nw + b];
    if (b == 0) sop = opidx[o];
    __syncthreads();

    const unsigned long long* sk = skey + (size_t)b * in;
    float res;
    if (sop == 0) {                 // min, identity 1.0
        res = 1.0f;
        for (int k = 0; k < in; ++k) {
            unsigned long long kv = sk[k];
            unsigned idx = (unsigned)(kv & 0xffffffffu);
            if ((mrow[idx >> 5] >> (idx & 31)) & 1u) {
                res = __uint_as_float((unsigned)(kv >> 32));
                break;
            }
        }
    } else {                        // max, identity 0.0
        res = 0.0f;
        for (int k = in - 1; k >= 0; --k) {
            unsigned long long kv = sk[k];
            unsigned idx = (unsigned)(kv & 0xffffffffu);
            if ((mrow[idx >> 5] >> (idx & 31)) & 1u) {
                res = __uint_as_float((unsigned)(kv >> 32));
                break;
            }
        }
    }
    outp[(size_t)b * out + o] = res;
}

// ---------------------------------------------------------------------------
extern "C" void kernel_launch(void* const* d_in, const int* in_sizes, int n_in,
                              void* d_out, int out_size) {
    const float* x    = (const float*)d_in[0];
    const float* etc0 = (const float*)d_in[1];
    const float* otc0 = (const float*)d_in[2];
    const float* etc1 = (const float*)d_in[3];
    const float* otc1 = (const float*)d_in[4];
    float* out = (float*)d_out;

    // --- JAX key chain (partitionable threefry), base = key(42) = (0, 42) ---
    uint32_t l0k0, l0k1, l1k0, l1k1;
    tf2x32(0u, 42u, 0u, 0u, l0k0, l0k1);   // fold_in(base, 0)
    tf2x32(0u, 42u, 0u, 1u, l1k0, l1k1);   // fold_in(base, 1)

    uint32_t op0k0, op0k1, e0k0, e0k1;
    tf2x32(l0k0, l0k1, 0u, 0u, op0k0, op0k1);   // split[0] = k_op
    tf2x32(l0k0, l0k1, 0u, 1u, e0k0,  e0k1);    // split[1] = k_edge
    uint32_t op1k0, op1k1, e1k0, e1k1;
    tf2x32(l1k0, l1k1, 0u, 0u, op1k0, op1k1);
    tf2x32(l1k0, l1k1, 0u, 1u, e1k0,  e1k1);

    void *p_op0, *p_op1, *p_m0, *p_m1, *p_s0, *p_s1, *p_h;
    cudaGetSymbolAddress(&p_op0, g_op0);
    cudaGetSymbolAddress(&p_op1, g_op1);
    cudaGetSymbolAddress(&p_m0,  g_mask0);
    cudaGetSymbolAddress(&p_m1,  g_mask1);
    cudaGetSymbolAddress(&p_s0,  g_skey0);
    cudaGetSymbolAddress(&p_s1,  g_skey1);
    cudaGetSymbolAddress(&p_h,   g_h);

    // --- layer 0: in=1024, out=512 ---
    op_kernel<<<(F1 + 127) / 128, 128>>>(op0k0, op0k1, otc0, (int*)p_op0, F1);
    mask_kernel<<<(F1 * F0) / 256, 256>>>(e0k0, e0k1, etc0, (const int*)p_op0,
                                          (uint32_t*)p_m0, F0, 10);
    sort_kernel<<<B_SZ, 256>>>(x, (unsigned long long*)p_s0, F0);
    probe_kernel<<<F1, B_SZ>>>((const unsigned long long*)p_s0, (const uint32_t*)p_m0,
                               (const int*)p_op0, (float*)p_h, F1, F0);

    // --- layer 1: in=512, out=1024 ---
    op_kernel<<<(F0 + 127) / 128, 128>>>(op1k0, op1k1, otc1, (int*)p_op1, F0);
    mask_kernel<<<(F0 * F1) / 256, 256>>>(e1k0, e1k1, etc1, (const int*)p_op1,
                                          (uint32_t*)p_m1, F1, 9);
    sort_kernel<<<B_SZ, 256>>>((const float*)p_h, (unsigned long long*)p_s1, F1);
    probe_kernel<<<F0, B_SZ>>>((const unsigned long long*)p_s1, (const uint32_t*)p_m1,
                               (const int*)p_op1, out, F0, F1);
}

// round 4
// speedup vs baseline: 1.0769x; 1.0769x over previous
#include <cuda_runtime.h>
#include <cstdint>

// ---------------------------------------------------------------------------
// Threefry-2x32, FULL 20 rounds + 6 key injections (bit-exact JAX).
// ---------------------------------------------------------------------------
#define TF_ROUND(r) do { x0 += x1; x1 = (x1 << (r)) | (x1 >> (32 - (r))); x1 ^= x0; } while (0)

__host__ __device__ __forceinline__ void tf2x32(uint32_t k0, uint32_t k1,
                                                uint32_t x0, uint32_t x1,
                                                uint32_t& o0, uint32_t& o1) {
    uint32_t k2 = k0 ^ k1 ^ 0x1BD11BDAu;
    x0 += k0; x1 += k1;
    TF_ROUND(13); TF_ROUND(15); TF_ROUND(26); TF_ROUND(6);
    x0 += k1; x1 += k2 + 1u;
    TF_ROUND(17); TF_ROUND(29); TF_ROUND(16); TF_ROUND(24);
    x0 += k2; x1 += k0 + 2u;
    TF_ROUND(13); TF_ROUND(15); TF_ROUND(26); TF_ROUND(6);
    x0 += k0; x1 += k1 + 3u;
    TF_ROUND(17); TF_ROUND(29); TF_ROUND(16); TF_ROUND(24);
    x0 += k1; x1 += k2 + 4u;
    TF_ROUND(13); TF_ROUND(15); TF_ROUND(26); TF_ROUND(6);
    x0 += k2; x1 += k0 + 5u;
    o0 = x0; o1 = x1;
}

// Partitionable random_bits: element j -> block (0, j), draw = o0 ^ o1.
__device__ __forceinline__ uint32_t tfbits(uint32_t k0, uint32_t k1, uint32_t j) {
    uint32_t o0, o1;
    tf2x32(k0, k1, 0u, j, o0, o1);
    return o0 ^ o1;
}

__device__ __forceinline__ float jax_uniform(uint32_t bits) {
    const float TINY = 1.17549435e-38f;
    float f = __uint_as_float((bits >> 9) | 0x3f800000u) - 1.0f;
    return fmaxf(TINY, f + TINY);
}

// argmax(c + gumbel) over 2; index-0 wins ties. Equal counts -> exact bit compare.
__device__ __forceinline__ bool decide(float c0, float c1, uint32_t b0, uint32_t b1) {
    if (c0 == c1) return (b1 >> 9) > (b0 >> 9);
    float g0 = -logf(-logf(jax_uniform(b0)));
    float g1 = -logf(-logf(jax_uniform(b1)));
    return (c1 + g1) > (c0 + g0);
}

// ---------------------------------------------------------------------------
#define B_SZ  128
#define F0    1024
#define F1    512

__device__ int                 g_op0[F1];
__device__ int                 g_op1[F0];
__device__ uint32_t            g_mask0[F1 * (F0 / 32)];
__device__ uint32_t            g_mask1[F0 * (F1 / 32)];
__device__ unsigned long long  g_skeyT0[F0 * B_SZ];   // transposed [k][b]
__device__ unsigned long long  g_skeyT1[F1 * B_SZ];
__device__ float               g_hT[F1 * B_SZ];       // hidden, transposed [o][b]

// ---------------------------------------------------------------------------
// MEGA kernel: blocks [0,128)   = sort layer-0 input rows (depends on x only)
//              blocks [128,384) = layer-0 op + edge masks (depends on etc0/otc0)
//              blocks [384,640) = layer-1 op + edge masks (depends on etc1/otc1)
// ---------------------------------------------------------------------------
__global__ void mega_kernel(const float* __restrict__ x,
                            const float* __restrict__ etc0, const float* __restrict__ otc0,
                            const float* __restrict__ etc1, const float* __restrict__ otc1,
                            uint32_t op0k0, uint32_t op0k1, uint32_t e0k0, uint32_t e0k1,
                            uint32_t op1k0, uint32_t op1k1, uint32_t e1k0, uint32_t e1k1) {
    __shared__ unsigned long long a[1024];
    int bid = blockIdx.x;
    int tid = threadIdx.x;

    if (bid < B_SZ) {
        // ---- bitonic sort of batch row `bid` over F0=1024 clamped values ----
        int b = bid;
        for (int idx = tid; idx < F0; idx += 256) {
            float v = fmaxf(x[(size_t)b * F0 + idx], 0.0f);
            a[idx] = ((unsigned long long)__float_as_uint(v) << 32) | (unsigned)idx;
        }
        __syncthreads();
        for (int k = 2; k <= F0; k <<= 1) {
            for (int j = k >> 1; j > 0; j >>= 1) {
                for (int s = tid; s < F0; s += 256) {
                    int l = s ^ j;
                    if (l > s) {
                        bool up = ((s & k) == 0);
                        unsigned long long va = a[s], vb = a[l];
                        if ((va > vb) == up) { a[s] = vb; a[l] = va; }
                    }
                }
                __syncthreads();
            }
        }
        for (int idx = tid; idx < F0; idx += 256)
            g_skeyT0[(size_t)idx * B_SZ + b] = a[idx];   // transposed store
        return;
    }

    // ---- mask blocks ----
    int warp = tid >> 5, lane = tid & 31;
    int o, wslice, log2in;
    const float* etc; const float* otc;
    uint32_t ek0, ek1, opk0, opk1;
    uint32_t* maskb; int* oparr;
    if (bid < 384) {              // layer 0: out=512, in=1024, 4 warps per o
        int q = bid - 128;        // 0..255
        o = q * 2 + (warp >> 2); wslice = warp & 3;
        log2in = 10; etc = etc0; otc = otc0;
        ek0 = e0k0; ek1 = e0k1; opk0 = op0k0; opk1 = op0k1;
        maskb = g_mask0; oparr = g_op0;
    } else {                      // layer 1: out=1024, in=512, 2 warps per o
        int q = bid - 384;        // 0..255
        o = q * 4 + (warp >> 1); wslice = warp & 1;
        log2in = 9; etc = etc1; otc = otc1;
        ek0 = e1k0; ek1 = e1k1; opk0 = op1k0; opk1 = op1k1;
        maskb = g_mask1; oparr = g_op1;
    }

    // operator selection, lane-split: lane0/lane1 each compute one draw, shfl both
    uint32_t jv = tfbits(opk0, opk1, (uint32_t)(2 * o) + (uint32_t)(lane & 1));
    uint32_t ob0 = __shfl_sync(0xffffffffu, jv, 0);
    uint32_t ob1 = __shfl_sync(0xffffffffu, jv, 1);
    int op = decide(otc[2 * o], otc[2 * o + 1], ob0, ob1) ? 1 : 0;
    if (wslice == 0 && lane == 0) oparr[o] = op;

    int nw = 1 << (log2in - 5);
    uint32_t mbase = ((uint32_t)(o * 2 + op)) << log2in;
    const float2* etc2 = (const float2*)etc;

    #pragma unroll 2
    for (int c = 0; c < 8; ++c) {
        int i = wslice * 256 + c * 32 + lane;
        uint32_t m = mbase + (uint32_t)i;
        uint32_t b0 = tfbits(ek0, ek1, 2u * m);        // et=0 (no_edge)
        uint32_t b1 = tfbits(ek0, ek1, 2u * m + 1u);   // et=1 (normal_edge)
        float2 cc = etc2[m];
        bool sel = decide(cc.x, cc.y, b0, b1);
        unsigned msk = __ballot_sync(0xffffffffu, sel);
        if (lane == 0) maskb[o * nw + (i >> 5)] = msk;
    }
}

// ---------------------------------------------------------------------------
// Probe: block = neuron o, thread = batch b. Coalesced loads from skeyT.
// writeT: outp is [o][B] (hidden, transposed). else outp is [B][out] (final).
// ---------------------------------------------------------------------------
template <bool WRITE_T>
__global__ void probe_kernel_t(const unsigned long long* __restrict__ skeyT,
                               const uint32_t* __restrict__ maskbits,
                               const int* __restrict__ opidx,
                               float* __restrict__ outp, int out, int in) {
    int o = blockIdx.x;
    int b = threadIdx.x;
    __shared__ uint32_t mrow[32];
    __shared__ int sop;
    int nw = in >> 5;
    if (b < nw) mrow[b] = maskbits[o * nw + b];
    if (b == 0) sop = opidx[o];
    __syncthreads();

    float res;
    if (sop == 0) {                 // min, identity 1.0
        res = 1.0f;
        for (int k = 0; k < in; ++k) {
            unsigned long long kv = skeyT[(size_t)k * B_SZ + b];
            unsigned idx = (unsigned)(kv & 0xffffffffu);
            if ((mrow[idx >> 5] >> (idx & 31)) & 1u) {
                res = __uint_as_float((unsigned)(kv >> 32));
                break;
            }
        }
    } else {                        // max, identity 0.0
        res = 0.0f;
        for (int k = in - 1; k >= 0; --k) {
            unsigned long long kv = skeyT[(size_t)k * B_SZ + b];
            unsigned idx = (unsigned)(kv & 0xffffffffu);
            if ((mrow[idx >> 5] >> (idx & 31)) & 1u) {
                res = __uint_as_float((unsigned)(kv >> 32));
                break;
            }
        }
    }
    if (WRITE_T) outp[(size_t)o * B_SZ + b] = res;          // coalesced
    else         outp[(size_t)b * out + o] = res;           // final layout [B,out]
}

// ---------------------------------------------------------------------------
// Sort layer-1 hidden rows (n=512), reading transposed hT, writing skeyT1.
// ---------------------------------------------------------------------------
__global__ void sort1_kernel(const float* __restrict__ hT,
                             unsigned long long* __restrict__ skeyT) {
    __shared__ unsigned long long a[512];
    int b = blockIdx.x;
    int tid = threadIdx.x;
    for (int idx = tid; idx < F1; idx += 256) {
        float v = fmaxf(hT[(size_t)idx * B_SZ + b], 0.0f);
        a[idx] = ((unsigned long long)__float_as_uint(v) << 32) | (unsigned)idx;
    }
    __syncthreads();
    for (int k = 2; k <= F1; k <<= 1) {
        for (int j = k >> 1; j > 0; j >>= 1) {
            for (int s = tid; s < F1; s += 256) {
                int l = s ^ j;
                if (l > s) {
                    bool up = ((s & k) == 0);
                    unsigned long long va = a[s], vb = a[l];
                    if ((va > vb) == up) { a[s] = vb; a[l] = va; }
                }
            }
            __syncthreads();
        }
    }
    for (int idx = tid; idx < F1; idx += 256)
        skeyT[(size_t)idx * B_SZ + b] = a[idx];
}

// ---------------------------------------------------------------------------
extern "C" void kernel_launch(void* const* d_in, const int* in_sizes, int n_in,
                              void* d_out, int out_size) {
    const float* x    = (const float*)d_in[0];
    const float* etc0 = (const float*)d_in[1];
    const float* otc0 = (const float*)d_in[2];
    const float* etc1 = (const float*)d_in[3];
    const float* otc1 = (const float*)d_in[4];
    float* out = (float*)d_out;

    // JAX key chain (partitionable), base = key(42) = (0, 42)
    uint32_t l0k0, l0k1, l1k0, l1k1;
    tf2x32(0u, 42u, 0u, 0u, l0k0, l0k1);
    tf2x32(0u, 42u, 0u, 1u, l1k0, l1k1);
    uint32_t op0k0, op0k1, e0k0, e0k1;
    tf2x32(l0k0, l0k1, 0u, 0u, op0k0, op0k1);
    tf2x32(l0k0, l0k1, 0u, 1u, e0k0,  e0k1);
    uint32_t op1k0, op1k1, e1k0, e1k1;
    tf2x32(l1k0, l1k1, 0u, 0u, op1k0, op1k1);
    tf2x32(l1k0, l1k1, 0u, 1u, e1k0,  e1k1);

    void *p_op0, *p_op1, *p_m0, *p_m1, *p_s0, *p_s1, *p_h;
    cudaGetSymbolAddress(&p_op0, g_op0);
    cudaGetSymbolAddress(&p_op1, g_op1);
    cudaGetSymbolAddress(&p_m0,  g_mask0);
    cudaGetSymbolAddress(&p_m1,  g_mask1);
    cudaGetSymbolAddress(&p_s0,  g_skeyT0);
    cudaGetSymbolAddress(&p_s1,  g_skeyT1);
    cudaGetSymbolAddress(&p_h,   g_hT);

    // 1) all input-only work in one launch: sort0 + ops + masks (both layers)
    mega_kernel<<<640, 256>>>(x, etc0, otc0, etc1, otc1,
                              op0k0, op0k1, e0k0, e0k1,
                              op1k0, op1k1, e1k0, e1k1);
    // 2) layer-0 probe -> hidden (transposed)
    probe_kernel_t<true><<<F1, B_SZ>>>((const unsigned long long*)p_s0,
                                       (const uint32_t*)p_m0, (const int*)p_op0,
                                       (float*)p_h, F1, F0);
    // 3) sort hidden rows
    sort1_kernel<<<B_SZ, 256>>>((const float*)p_h, (unsigned long long*)p_s1);
    // 4) layer-1 probe -> final output [B, F0]
    probe_kernel_t<false><<<F0, B_SZ>>>((const unsigned long long*)p_s1,
                                        (const uint32_t*)p_m1, (const int*)p_op1,
                                        out, F0, F1);
}

// round 5
// speedup vs baseline: 1.2973x; 1.2046x over previous
#include <cuda_runtime.h>
#include <cstdint>

// ---------------------------------------------------------------------------
// Threefry-2x32, FULL 20 rounds + 6 key injections (bit-exact JAX).
// ---------------------------------------------------------------------------
#define TF_ROUND(r) do { x0 += x1; x1 = (x1 << (r)) | (x1 >> (32 - (r))); x1 ^= x0; } while (0)

__host__ __device__ __forceinline__ void tf2x32(uint32_t k0, uint32_t k1,
                                                uint32_t x0, uint32_t x1,
                                                uint32_t& o0, uint32_t& o1) {
    uint32_t k2 = k0 ^ k1 ^ 0x1BD11BDAu;
    x0 += k0; x1 += k1;
    TF_ROUND(13); TF_ROUND(15); TF_ROUND(26); TF_ROUND(6);
    x0 += k1; x1 += k2 + 1u;
    TF_ROUND(17); TF_ROUND(29); TF_ROUND(16); TF_ROUND(24);
    x0 += k2; x1 += k0 + 2u;
    TF_ROUND(13); TF_ROUND(15); TF_ROUND(26); TF_ROUND(6);
    x0 += k0; x1 += k1 + 3u;
    TF_ROUND(17); TF_ROUND(29); TF_ROUND(16); TF_ROUND(24);
    x0 += k1; x1 += k2 + 4u;
    TF_ROUND(13); TF_ROUND(15); TF_ROUND(26); TF_ROUND(6);
    x0 += k2; x1 += k0 + 5u;
    o0 = x0; o1 = x1;
}

__device__ __forceinline__ uint32_t tfbits(uint32_t k0, uint32_t k1, uint32_t j) {
    uint32_t o0, o1;
    tf2x32(k0, k1, 0u, j, o0, o1);
    return o0 ^ o1;
}

__device__ __forceinline__ float jax_uniform(uint32_t bits) {
    const float TINY = 1.17549435e-38f;
    float f = __uint_as_float((bits >> 9) | 0x3f800000u) - 1.0f;
    return fmaxf(TINY, f + TINY);
}

// argmax(c + gumbel) over 2; index-0 wins ties. Equal counts -> exact bit compare.
__device__ __forceinline__ bool decide(float c0, float c1, uint32_t b0, uint32_t b1) {
    if (c0 == c1) return (b1 >> 9) > (b0 >> 9);
    float g0 = -logf(-logf(jax_uniform(b0)));
    float g1 = -logf(-logf(jax_uniform(b1)));
    return (c1 + g1) > (c0 + g0);
}

// ---------------------------------------------------------------------------
#define B_SZ  128
#define F0    1024
#define F1    512

__device__ int                 g_op0[F1];
__device__ int                 g_op1[F0];
__device__ uint32_t            g_mask0[F1 * (F0 / 32)];   // 64 KB
__device__ uint32_t            g_mask1[F0 * (F1 / 32)];   // 64 KB
__device__ unsigned long long  g_skey0[B_SZ * F0];        // sorted keys, [b][k]

// ---------------------------------------------------------------------------
// MEGA kernel: blocks [0,128)   = sort layer-0 input rows
//              blocks [128,384) = layer-0 op + edge masks
//              blocks [384,640) = layer-1 op + edge masks
// ---------------------------------------------------------------------------
__global__ void mega_kernel(const float* __restrict__ x,
                            const float* __restrict__ etc0, const float* __restrict__ otc0,
                            const float* __restrict__ etc1, const float* __restrict__ otc1,
                            uint32_t op0k0, uint32_t op0k1, uint32_t e0k0, uint32_t e0k1,
                            uint32_t op1k0, uint32_t op1k1, uint32_t e1k0, uint32_t e1k1) {
    __shared__ unsigned long long a[1024];
    int bid = blockIdx.x;
    int tid = threadIdx.x;

    if (bid < B_SZ) {
        int b = bid;
        for (int idx = tid; idx < F0; idx += 256) {
            float v = fmaxf(x[(size_t)b * F0 + idx], 0.0f);
            a[idx] = ((unsigned long long)__float_as_uint(v) << 32) | (unsigned)idx;
        }
        __syncthreads();
        for (int k = 2; k <= F0; k <<= 1) {
            for (int j = k >> 1; j > 0; j >>= 1) {
                for (int s = tid; s < F0; s += 256) {
                    int l = s ^ j;
                    if (l > s) {
                        bool up = ((s & k) == 0);
                        unsigned long long va = a[s], vb = a[l];
                        if ((va > vb) == up) { a[s] = vb; a[l] = va; }
                    }
                }
                __syncthreads();
            }
        }
        for (int idx = tid; idx < F0; idx += 256)
            g_skey0[(size_t)b * F0 + idx] = a[idx];     // contiguous row
        return;
    }

    // ---- mask blocks ----
    int warp = tid >> 5, lane = tid & 31;
    int o, wslice, log2in;
    const float* etc; const float* otc;
    uint32_t ek0, ek1, opk0, opk1;
    uint32_t* maskb; int* oparr;
    if (bid < 384) {              // layer 0: out=512, in=1024, 4 warps per o
        int q = bid - 128;
        o = q * 2 + (warp >> 2); wslice = warp & 3;
        log2in = 10; etc = etc0; otc = otc0;
        ek0 = e0k0; ek1 = e0k1; opk0 = op0k0; opk1 = op0k1;
        maskb = g_mask0; oparr = g_op0;
    } else {                      // layer 1: out=1024, in=512, 2 warps per o
        int q = bid - 384;
        o = q * 4 + (warp >> 1); wslice = warp & 1;
        log2in = 9; etc = etc1; otc = otc1;
        ek0 = e1k0; ek1 = e1k1; opk0 = op1k0; opk1 = op1k1;
        maskb = g_mask1; oparr = g_op1;
    }

    // operator selection: lanes 0/1 compute one draw each, shfl both
    uint32_t jv = tfbits(opk0, opk1, (uint32_t)(2 * o) + (uint32_t)(lane & 1));
    uint32_t ob0 = __shfl_sync(0xffffffffu, jv, 0);
    uint32_t ob1 = __shfl_sync(0xffffffffu, jv, 1);
    int op = decide(otc[2 * o], otc[2 * o + 1], ob0, ob1) ? 1 : 0;
    if (wslice == 0 && lane == 0) oparr[o] = op;

    int nw = 1 << (log2in - 5);
    uint32_t mbase = ((uint32_t)(o * 2 + op)) << log2in;
    const float2* etc2 = (const float2*)etc;

    #pragma unroll 2
    for (int c = 0; c < 8; ++c) {
        int i = wslice * 256 + c * 32 + lane;
        uint32_t m = mbase + (uint32_t)i;
        uint32_t b0 = tfbits(ek0, ek1, 2u * m);        // et=0 (no_edge)
        uint32_t b1 = tfbits(ek0, ek1, 2u * m + 1u);   // et=1 (normal_edge)
        float2 cc = etc2[m];
        bool sel = decide(cc.x, cc.y, b0, b1);
        unsigned msk = __ballot_sync(0xffffffffu, sel);
        if (lane == 0) maskb[o * nw + (i >> 5)] = msk;
    }
}

// ---------------------------------------------------------------------------
// FUSED per-batch-row kernel: block = row b.
//  1) load sorted layer-0 keys into smem
//  2) probe layer-0 (512 neurons, 2 per thread) -> hidden keys in smem
//  3) bitonic sort 512 hidden keys
//  4) probe layer-1 (1024 neurons, 4 per thread) -> out[b][:]
// ---------------------------------------------------------------------------
__global__ __launch_bounds__(256) void fused_kernel(float* __restrict__ out) {
    __shared__ unsigned long long a[1024];
    __shared__ unsigned long long hk[512];
    int b = blockIdx.x;
    int tid = threadIdx.x;

    // 1) coalesced 16B loads of sorted row
    {
        const uint4* src = (const uint4*)(g_skey0 + (size_t)b * F0);
        uint4* dst = (uint4*)a;
        #pragma unroll
        for (int i = 0; i < 2; ++i)
            dst[tid + i * 256] = src[tid + i * 256];
    }
    __syncthreads();

    // 2) probe layer 0
    #pragma unroll
    for (int rep = 0; rep < 2; ++rep) {
        int o = tid + rep * 256;
        int op = g_op0[o];
        const uint32_t* mrow = g_mask0 + o * (F0 / 32);
        float res;
        if (op == 0) {
            res = 1.0f;
            for (int k = 0; k < F0; ++k) {
                unsigned long long kv = a[k];
                unsigned idx = (unsigned)kv;
                if ((mrow[idx >> 5] >> (idx & 31)) & 1u) {
                    res = __uint_as_float((unsigned)(kv >> 32));
                    break;
                }
            }
        } else {
            res = 0.0f;
            for (int k = F0 - 1; k >= 0; --k) {
                unsigned long long kv = a[k];
                unsigned idx = (unsigned)kv;
                if ((mrow[idx >> 5] >> (idx & 31)) & 1u) {
                    res = __uint_as_float((unsigned)(kv >> 32));
                    break;
                }
            }
        }
        // res >= 0 always (values in [0,1]) -> bits order numerically
        hk[o] = ((unsigned long long)__float_as_uint(res) << 32) | (unsigned)o;
    }
    __syncthreads();

    // 3) bitonic sort of 512 hidden keys
    for (int k = 2; k <= F1; k <<= 1) {
        for (int j = k >> 1; j > 0; j >>= 1) {
            #pragma unroll
            for (int r = 0; r < 2; ++r) {
                int s = tid + r * 256;
                int l = s ^ j;
                if (l > s) {
                    bool up = ((s & k) == 0);
                    unsigned long long va = hk[s], vb = hk[l];
                    if ((va > vb) == up) { hk[s] = vb; hk[l] = va; }
                }
            }
            __syncthreads();
        }
    }

    // 4) probe layer 1 -> final output
    #pragma unroll
    for (int rep = 0; rep < 4; ++rep) {
        int o = tid + rep * 256;
        int op = g_op1[o];
        const uint32_t* mrow = g_mask1 + o * (F1 / 32);
        float res;
        if (op == 0) {
            res = 1.0f;
            for (int k = 0; k < F1; ++k) {
                unsigned long long kv = hk[k];
                unsigned idx = (unsigned)kv;
                if ((mrow[idx >> 5] >> (idx & 31)) & 1u) {
                    res = __uint_as_float((unsigned)(kv >> 32));
                    break;
                }
            }
        } else {
            res = 0.0f;
            for (int k = F1 - 1; k >= 0; --k) {
                unsigned long long kv = hk[k];
                unsigned idx = (unsigned)kv;
                if ((mrow[idx >> 5] >> (idx & 31)) & 1u) {
                    res = __uint_as_float((unsigned)(kv >> 32));
                    break;
                }
            }
        }
        out[(size_t)b * F0 + o] = res;      // coalesced across tid
    }
}

// ---------------------------------------------------------------------------
extern "C" void kernel_launch(void* const* d_in, const int* in_sizes, int n_in,
                              void* d_out, int out_size) {
    const float* x    = (const float*)d_in[0];
    const float* etc0 = (const float*)d_in[1];
    const float* otc0 = (const float*)d_in[2];
    const float* etc1 = (const float*)d_in[3];
    const float* otc1 = (const float*)d_in[4];
    float* out = (float*)d_out;

    // JAX key chain (partitionable), base = key(42) = (0, 42)
    uint32_t l0k0, l0k1, l1k0, l1k1;
    tf2x32(0u, 42u, 0u, 0u, l0k0, l0k1);
    tf2x32(0u, 42u, 0u, 1u, l1k0, l1k1);
    uint32_t op0k0, op0k1, e0k0, e0k1;
    tf2x32(l0k0, l0k1, 0u, 0u, op0k0, op0k1);
    tf2x32(l0k0, l0k1, 0u, 1u, e0k0,  e0k1);
    uint32_t op1k0, op1k1, e1k0, e1k1;
    tf2x32(l1k0, l1k1, 0u, 0u, op1k0, op1k1);
    tf2x32(l1k0, l1k1, 0u, 1u, e1k0,  e1k1);

    // 1) input-only work: sort0 + ops + masks (both layers)
    mega_kernel<<<640, 256>>>(x, etc0, otc0, etc1, otc1,
                              op0k0, op0k1, e0k0, e0k1,
                              op1k0, op1k1, e1k0, e1k1);
    // 2) everything else, fused per batch row
    fused_kernel<<<B_SZ, 256>>>(out);
}

// round 6
// speedup vs baseline: 1.7231x; 1.3282x over previous
#include <cuda_runtime.h>
#include <cstdint>

// ---------------------------------------------------------------------------
// Threefry-2x32, FULL 20 rounds + 6 key injections (bit-exact JAX).
// ---------------------------------------------------------------------------
#define TF_ROUND(r) do { x0 += x1; x1 = (x1 << (r)) | (x1 >> (32 - (r))); x1 ^= x0; } while (0)

__host__ __device__ __forceinline__ void tf2x32(uint32_t k0, uint32_t k1,
                                                uint32_t x0, uint32_t x1,
                                                uint32_t& o0, uint32_t& o1) {
    uint32_t k2 = k0 ^ k1 ^ 0x1BD11BDAu;
    x0 += k0; x1 += k1;
    TF_ROUND(13); TF_ROUND(15); TF_ROUND(26); TF_ROUND(6);
    x0 += k1; x1 += k2 + 1u;
    TF_ROUND(17); TF_ROUND(29); TF_ROUND(16); TF_ROUND(24);
    x0 += k2; x1 += k0 + 2u;
    TF_ROUND(13); TF_ROUND(15); TF_ROUND(26); TF_ROUND(6);
    x0 += k0; x1 += k1 + 3u;
    TF_ROUND(17); TF_ROUND(29); TF_ROUND(16); TF_ROUND(24);
    x0 += k1; x1 += k2 + 4u;
    TF_ROUND(13); TF_ROUND(15); TF_ROUND(26); TF_ROUND(6);
    x0 += k2; x1 += k0 + 5u;
    o0 = x0; o1 = x1;
}

__device__ __forceinline__ uint32_t tfbits(uint32_t k0, uint32_t k1, uint32_t j) {
    uint32_t o0, o1;
    tf2x32(k0, k1, 0u, j, o0, o1);
    return o0 ^ o1;
}

__device__ __forceinline__ float jax_uniform(uint32_t bits) {
    const float TINY = 1.17549435e-38f;
    float f = __uint_as_float((bits >> 9) | 0x3f800000u) - 1.0f;
    return fmaxf(TINY, f + TINY);
}

// argmax(c + gumbel) over 2; index-0 wins ties. Equal counts -> exact bit compare.
__device__ __forceinline__ bool decide(float c0, float c1, uint32_t b0, uint32_t b1) {
    if (c0 == c1) return (b1 >> 9) > (b0 >> 9);
    float g0 = -logf(-logf(jax_uniform(b0)));
    float g1 = -logf(-logf(jax_uniform(b1)));
    return (c1 + g1) > (c0 + g0);
}

// ---------------------------------------------------------------------------
#define B_SZ  128
#define F0    1024
#define F1    512

__device__ int                 g_op0[F1];
__device__ int                 g_op1[F0];
__device__ uint32_t            g_mask0[F1 * (F0 / 32)];   // 64 KB
__device__ uint32_t            g_mask1[F0 * (F1 / 32)];   // 64 KB
__device__ unsigned long long  g_skey0[B_SZ * F0];        // sorted keys, [b][k]

// ---------------------------------------------------------------------------
// MEGA kernel (512 threads): blocks [0,128)   = sort layer-0 input rows
//                            blocks [128,256) = layer-0 op + edge masks
//                            blocks [256,384) = layer-1 op + edge masks
// ---------------------------------------------------------------------------
__global__ __launch_bounds__(512) void mega_kernel(
        const float* __restrict__ x,
        const float* __restrict__ etc0, const float* __restrict__ otc0,
        const float* __restrict__ etc1, const float* __restrict__ otc1,
        uint32_t op0k0, uint32_t op0k1, uint32_t e0k0, uint32_t e0k1,
        uint32_t op1k0, uint32_t op1k1, uint32_t e1k0, uint32_t e1k1) {
    __shared__ unsigned long long a[1024];
    int bid = blockIdx.x;
    int tid = threadIdx.x;

    if (bid < B_SZ) {
        int b = bid;
        #pragma unroll
        for (int r = 0; r < 2; ++r) {
            int idx = tid + r * 512;
            float v = fmaxf(x[(size_t)b * F0 + idx], 0.0f);
            a[idx] = ((unsigned long long)__float_as_uint(v) << 32) | (unsigned)idx;
        }
        __syncthreads();
        for (int k = 2; k <= F0; k <<= 1) {
            for (int j = k >> 1; j > 0; j >>= 1) {
                #pragma unroll
                for (int r = 0; r < 2; ++r) {
                    int s = tid + r * 512;
                    int l = s ^ j;
                    if (l > s) {
                        bool up = ((s & k) == 0);
                        unsigned long long va = a[s], vb = a[l];
                        if ((va > vb) == up) { a[s] = vb; a[l] = va; }
                    }
                }
                __syncthreads();
            }
        }
        #pragma unroll
        for (int r = 0; r < 2; ++r) {
            int idx = tid + r * 512;
            g_skey0[(size_t)b * F0 + idx] = a[idx];
        }
        return;
    }

    // ---- mask blocks ----
    int warp = tid >> 5, lane = tid & 31;
    int o, wslice, log2in;
    const float* etc; const float* otc;
    uint32_t ek0, ek1, opk0, opk1;
    uint32_t* maskb; int* oparr;
    if (bid < 256) {              // layer 0: out=512, in=1024, 4 warps per o
        int q = bid - 128;        // 0..127
        o = q * 4 + (warp >> 2); wslice = warp & 3;
        log2in = 10; etc = etc0; otc = otc0;
        ek0 = e0k0; ek1 = e0k1; opk0 = op0k0; opk1 = op0k1;
        maskb = g_mask0; oparr = g_op0;
    } else {                      // layer 1: out=1024, in=512, 2 warps per o
        int q = bid - 256;        // 0..127
        o = q * 8 + (warp >> 1); wslice = warp & 1;
        log2in = 9; etc = etc1; otc = otc1;
        ek0 = e1k0; ek1 = e1k1; opk0 = op1k0; opk1 = op1k1;
        maskb = g_mask1; oparr = g_op1;
    }

    // operator selection: lanes 0/1 compute one draw each, shfl both
    uint32_t jv = tfbits(opk0, opk1, (uint32_t)(2 * o) + (uint32_t)(lane & 1));
    uint32_t ob0 = __shfl_sync(0xffffffffu, jv, 0);
    uint32_t ob1 = __shfl_sync(0xffffffffu, jv, 1);
    int op = decide(otc[2 * o], otc[2 * o + 1], ob0, ob1) ? 1 : 0;
    if (wslice == 0 && lane == 0) oparr[o] = op;

    int nw = 1 << (log2in - 5);
    uint32_t mbase = ((uint32_t)(o * 2 + op)) << log2in;
    const float2* etc2 = (const float2*)etc;

    #pragma unroll 2
    for (int c = 0; c < 8; ++c) {
        int i = wslice * 256 + c * 32 + lane;
        uint32_t m = mbase + (uint32_t)i;
        uint32_t b0 = tfbits(ek0, ek1, 2u * m);        // et=0 (no_edge)
        uint32_t b1 = tfbits(ek0, ek1, 2u * m + 1u);   // et=1 (normal_edge)
        float2 cc = etc2[m];
        bool sel = decide(cc.x, cc.y, b0, b1);
        unsigned msk = __ballot_sync(0xffffffffu, sel);
        if (lane == 0) maskb[o * nw + (i >> 5)] = msk;
    }
}

// ---------------------------------------------------------------------------
// Batched probe: walk sorted keys in chunks of 8 with prefetched keys + mask
// words (MLP=8), branch-free tests. dir=+1 ascending (min), -1 descending (max).
// ---------------------------------------------------------------------------
__device__ __forceinline__ float probe8(const unsigned long long* __restrict__ a,
                                        int n, const uint32_t* __restrict__ mrow,
                                        int op) {
    float res;
    if (op == 0) {
        res = 1.0f;
        for (int base = 0; base < n; base += 8) {
            unsigned long long kv[8];
            uint32_t w[8];
            #pragma unroll
            for (int t = 0; t < 8; ++t) kv[t] = a[base + t];
            #pragma unroll
            for (int t = 0; t < 8; ++t) {
                unsigned idx = (unsigned)kv[t];
                w[t] = mrow[idx >> 5] >> (idx & 31);
            }
            bool found = false;
            #pragma unroll
            for (int t = 0; t < 8; ++t)
                if (!found && (w[t] & 1u)) {
                    res = __uint_as_float((unsigned)(kv[t] >> 32));
                    found = true;
                }
            if (found) break;
        }
    } else {
        res = 0.0f;
        for (int base = n - 8; base >= 0; base -= 8) {
            unsigned long long kv[8];
            uint32_t w[8];
            #pragma unroll
            for (int t = 0; t < 8; ++t) kv[t] = a[base + 7 - t];   // descending
            #pragma unroll
            for (int t = 0; t < 8; ++t) {
                unsigned idx = (unsigned)kv[t];
                w[t] = mrow[idx >> 5] >> (idx & 31);
            }
            bool found = false;
            #pragma unroll
            for (int t = 0; t < 8; ++t)
                if (!found && (w[t] & 1u)) {
                    res = __uint_as_float((unsigned)(kv[t] >> 32));
                    found = true;
                }
            if (found) break;
        }
    }
    return res;
}

// ---------------------------------------------------------------------------
// FUSED per-batch-row kernel (512 threads): block = row b.
// ---------------------------------------------------------------------------
__global__ __launch_bounds__(512) void fused_kernel(float* __restrict__ out) {
    __shared__ unsigned long long a[1024];
    __shared__ unsigned long long hk[512];
    int b = blockIdx.x;
    int tid = threadIdx.x;

    // 1) coalesced 16B loads of sorted row (1024 keys = 512 uint4)
    {
        const uint4* src = (const uint4*)(g_skey0 + (size_t)b * F0);
        ((uint4*)a)[tid] = src[tid];
    }
    __syncthreads();

    // 2) probe layer 0 (1 neuron per thread)
    {
        int o = tid;
        int op = g_op0[o];
        float res = probe8(a, F0, g_mask0 + o * (F0 / 32), op);
        // res >= 0 always -> float bits order numerically
        hk[o] = ((unsigned long long)__float_as_uint(res) << 32) | (unsigned)o;
    }
    __syncthreads();

    // 3) bitonic sort of 512 hidden keys (1 compare-exchange slot per thread)
    for (int k = 2; k <= F1; k <<= 1) {
        for (int j = k >> 1; j > 0; j >>= 1) {
            int s = tid;
            int l = s ^ j;
            if (l > s) {
                bool up = ((s & k) == 0);
                unsigned long long va = hk[s], vb = hk[l];
                if ((va > vb) == up) { hk[s] = vb; hk[l] = va; }
            }
            __syncthreads();
        }
    }

    // 4) probe layer 1 (2 neurons per thread) -> final output
    #pragma unroll
    for (int rep = 0; rep < 2; ++rep) {
        int o = tid + rep * 512;
        int op = g_op1[o];
        float res = probe8(hk, F1, g_mask1 + o * (F1 / 32), op);
        out[(size_t)b * F0 + o] = res;      // coalesced across tid
    }
}

// ---------------------------------------------------------------------------
extern "C" void kernel_launch(void* const* d_in, const int* in_sizes, int n_in,
                              void* d_out, int out_size) {
    const float* x    = (const float*)d_in[0];
    const float* etc0 = (const float*)d_in[1];
    const float* otc0 = (const float*)d_in[2];
    const float* etc1 = (const float*)d_in[3];
    const float* otc1 = (const float*)d_in[4];
    float* out = (float*)d_out;

    // JAX key chain (partitionable), base = key(42) = (0, 42)
    uint32_t l0k0, l0k1, l1k0, l1k1;
    tf2x32(0u, 42u, 0u, 0u, l0k0, l0k1);
    tf2x32(0u, 42u, 0u, 1u, l1k0, l1k1);
    uint32_t op0k0, op0k1, e0k0, e0k1;
    tf2x32(l0k0, l0k1, 0u, 0u, op0k0, op0k1);
    tf2x32(l0k0, l0k1, 0u, 1u, e0k0,  e0k1);
    uint32_t op1k0, op1k1, e1k0, e1k1;
    tf2x32(l1k0, l1k1, 0u, 0u, op1k0, op1k1);
    tf2x32(l1k0, l1k1, 0u, 1u, e1k0,  e1k1);

    // 1) input-only work: sort0 + ops + masks (both layers)
    mega_kernel<<<384, 512>>>(x, etc0, otc0, etc1, otc1,
                              op0k0, op0k1, e0k0, e0k1,
                              op1k0, op1k1, e1k0, e1k1);
    // 2) everything else, fused per batch row
    fused_kernel<<<B_SZ, 512>>>(out);
}